// round 9
// baseline (speedup 1.0000x reference)
#include <cuda_runtime.h>
#include <cstdint>

#define BN_EPS   1e-3f
#define DIN      128
#define DOUT     256
#define MT       128
#define NTHREADS 512

// smem (floats): sW[32768] | sA[16 warps][1024] | sScale[256] | sBias[256]
#define SMEM_FLOATS (32768 + 16384 + 256 + 256)
#define SMEM_BYTES  (SMEM_FLOATS * 4)

__device__ __forceinline__ void ffma2(unsigned long long &d, unsigned long long a, unsigned long long b) {
    asm("fma.rn.f32x2 %0, %1, %2, %0;" : "+l"(d) : "l"(a), "l"(b));
}
__device__ __forceinline__ unsigned long long dup2(float x) {
    unsigned long long r;
    asm("mov.b64 %0, {%1, %1};" : "=l"(r) : "f"(x));
    return r;
}
__device__ __forceinline__ void unpack2(unsigned long long v, float &lo, float &hi) {
    asm("mov.b64 {%0, %1}, %2;" : "=f"(lo), "=f"(hi) : "l"(v));
}
__device__ __forceinline__ void cp_async16(float* dst_smem, const float* src) {
    unsigned s = (unsigned)__cvta_generic_to_shared(dst_smem);
    asm volatile("cp.async.cg.shared.global [%0], [%1], 16;" :: "r"(s), "l"(src));
}
#define CP_COMMIT() asm volatile("cp.async.commit_group;")
#define CP_WAIT0()  asm volatile("cp.async.wait_group 0;")

__global__ __launch_bounds__(NTHREADS, 1)
void attn_transformer_kernel(const float* __restrict__ inputs,
                             const float* __restrict__ priors,
                             const float* __restrict__ W,
                             const float* __restrict__ gamma,
                             const float* __restrict__ beta,
                             const float* __restrict__ mmean,
                             const float* __restrict__ mvar,
                             float* __restrict__ out,
                             int nTiles)
{
    extern __shared__ float smem[];
    float* sW     = smem;                    // [128][256]
    float* sAbase = smem + 32768;            // [16 warps][8][128]
    float* sScale = smem + 32768 + 16384;    // [256]
    float* sBias  = sScale + 256;            // [256]

    const int tid   = threadIdx.x;
    const int lane  = tid & 31;
    const int warp  = tid >> 5;
    const int lane4 = lane * 4;

    float* sA = sAbase + warp * 1024;        // this warp's private 8-row buffer

    // ---- prologue ----
    // W -> smem (all threads cooperate)
    #pragma unroll
    for (int j = 0; j < 16; ++j) {
        int idx = tid + NTHREADS * j;                // float4 idx [0,8192)
        cp_async16(sW + idx * 4, W + idx * 4);
    }
    // this warp's first A rows (8 rows x 128 floats = 256 x 16B chunks)
    {
        const float* Abase = inputs + ((size_t)blockIdx.x * MT + warp * 8) * DIN;
        #pragma unroll
        for (int j = 0; j < 8; ++j) {
            int c = lane + 32 * j;                   // 16B chunk [0,256)
            cp_async16(sA + c * 4, Abase + c * 4);
        }
    }
    CP_COMMIT();

    // fold BN into scale/bias
    if (tid < 256) {
        float inv = gamma[tid] * rsqrtf(mvar[tid] + BN_EPS);
        sScale[tid] = inv;
        sBias[tid]  = beta[tid] - mmean[tid] * inv;
    }

    CP_WAIT0();
    __syncthreads();     // W + consts visible to all warps; the ONLY CTA barrier

    for (int t = blockIdx.x; t < nTiles; t += gridDim.x) {
        // ---- GEMM: 8 rows x 8 cols per thread, packed f32x2 FFMA ----
        unsigned long long acc[8][4];
        #pragma unroll
        for (int i = 0; i < 8; ++i) {
            acc[i][0] = 0ull; acc[i][1] = 0ull; acc[i][2] = 0ull; acc[i][3] = 0ull;
        }

        #pragma unroll 2
        for (int kk = 0; kk < DIN; kk += 4) {
            float4 a4[8];
            #pragma unroll
            for (int i = 0; i < 8; ++i)
                a4[i] = *reinterpret_cast<const float4*>(&sA[i * DIN + kk]);
            #pragma unroll
            for (int q = 0; q < 4; ++q) {
                const float* wrow = &sW[(kk + q) * DOUT];
                ulonglong2 Blo = *reinterpret_cast<const ulonglong2*>(&wrow[lane4]);
                ulonglong2 Bhi = *reinterpret_cast<const ulonglong2*>(&wrow[128 + lane4]);
                #pragma unroll
                for (int i = 0; i < 8; ++i) {
                    float av = (q == 0) ? a4[i].x : (q == 1) ? a4[i].y
                             : (q == 2) ? a4[i].z : a4[i].w;
                    unsigned long long ad = dup2(av);
                    ffma2(acc[i][0], ad, Blo.x);
                    ffma2(acc[i][1], ad, Blo.y);
                    ffma2(acc[i][2], ad, Bhi.x);
                    ffma2(acc[i][3], ad, Bhi.y);
                }
            }
        }

        // ---- prefetch next tile's rows into the SAME buffer (GEMM reads are done);
        //      the long epilogue below covers the flight. Per-warp, no barrier. ----
        {
            int tn = t + gridDim.x;
            if (tn < nTiles) {
                const float* Abase = inputs + ((size_t)tn * MT + warp * 8) * DIN;
                #pragma unroll
                for (int j = 0; j < 8; ++j) {
                    int c = lane + 32 * j;
                    cp_async16(sA + c * 4, Abase + c * 4);
                }
            }
            CP_COMMIT();
        }

        // ---- epilogue: stream row pairs (keeps live registers low) ----
        const size_t row0 = (size_t)t * MT + warp * 8;

        #pragma unroll 1
        for (int pr = 0; pr < 4; ++pr) {
            const int iA = 2 * pr, iB = 2 * pr + 1;

            // BN consts from smem (cheap LDS, reloaded per pair to cut live regs)
            float4 scLo = *reinterpret_cast<const float4*>(&sScale[lane4]);
            float4 scHi = *reinterpret_cast<const float4*>(&sScale[128 + lane4]);
            float4 bLo  = *reinterpret_cast<const float4*>(&sBias[lane4]);
            float4 bHi  = *reinterpret_cast<const float4*>(&sBias[128 + lane4]);

            const float* prA = priors + (row0 + iA) * DOUT;
            const float* prB = priors + (row0 + iB) * DOUT;
            float4 pA0 = *reinterpret_cast<const float4*>(&prA[lane4]);
            float4 pA1 = *reinterpret_cast<const float4*>(&prA[128 + lane4]);
            float4 pB0 = *reinterpret_cast<const float4*>(&prB[lane4]);
            float4 pB1 = *reinterpret_cast<const float4*>(&prB[128 + lane4]);

            float za[8], zb[8];
            {
                float x0, x1, x2, x3, x4, x5, x6, x7;
                unpack2(acc[iA][0], x0, x1);
                unpack2(acc[iA][1], x2, x3);
                unpack2(acc[iA][2], x4, x5);
                unpack2(acc[iA][3], x6, x7);
                za[0] = fmaf(x0, scLo.x, bLo.x) * pA0.x;
                za[1] = fmaf(x1, scLo.y, bLo.y) * pA0.y;
                za[2] = fmaf(x2, scLo.z, bLo.z) * pA0.z;
                za[3] = fmaf(x3, scLo.w, bLo.w) * pA0.w;
                za[4] = fmaf(x4, scHi.x, bHi.x) * pA1.x;
                za[5] = fmaf(x5, scHi.y, bHi.y) * pA1.y;
                za[6] = fmaf(x6, scHi.z, bHi.z) * pA1.z;
                za[7] = fmaf(x7, scHi.w, bHi.w) * pA1.w;
                unpack2(acc[iB][0], x0, x1);
                unpack2(acc[iB][1], x2, x3);
                unpack2(acc[iB][2], x4, x5);
                unpack2(acc[iB][3], x6, x7);
                zb[0] = fmaf(x0, scLo.x, bLo.x) * pB0.x;
                zb[1] = fmaf(x1, scLo.y, bLo.y) * pB0.y;
                zb[2] = fmaf(x2, scLo.z, bLo.z) * pB0.z;
                zb[3] = fmaf(x3, scLo.w, bLo.w) * pB0.w;
                zb[4] = fmaf(x4, scHi.x, bHi.x) * pB1.x;
                zb[5] = fmaf(x5, scHi.y, bHi.y) * pB1.y;
                zb[6] = fmaf(x6, scHi.z, bHi.z) * pB1.z;
                zb[7] = fmaf(x7, scHi.w, bHi.w) * pB1.w;
            }

            // Michelot fixed point (two rows pipelined through the shfl chains)
            float sa = 0.f, sb = 0.f;
            #pragma unroll
            for (int j = 0; j < 8; ++j) { sa += za[j]; sb += zb[j]; }
            #pragma unroll
            for (int off = 16; off > 0; off >>= 1) {
                sa += __shfl_xor_sync(0xffffffffu, sa, off);
                sb += __shfl_xor_sync(0xffffffffu, sb, off);
            }
            float taua = (sa - 1.0f) * (1.0f / 256.0f);
            float taub = (sb - 1.0f) * (1.0f / 256.0f);
            float ca = 256.0f, cb = 256.0f;
            bool da = false, db = false;

            for (int it = 0; it < 64; ++it) {
                float psa = 0.f, pca = 0.f, psb = 0.f, pcb = 0.f;
                #pragma unroll
                for (int j = 0; j < 8; ++j) {
                    if (za[j] > taua) { psa += za[j]; pca += 1.0f; }
                    if (zb[j] > taub) { psb += zb[j]; pcb += 1.0f; }
                }
                #pragma unroll
                for (int off = 16; off > 0; off >>= 1) {
                    psa += __shfl_xor_sync(0xffffffffu, psa, off);
                    pca += __shfl_xor_sync(0xffffffffu, pca, off);
                    psb += __shfl_xor_sync(0xffffffffu, psb, off);
                    pcb += __shfl_xor_sync(0xffffffffu, pcb, off);
                }
                if (!da) {
                    if (pca == ca) da = true;
                    else { ca = pca; taua = (psa - 1.0f) / pca; }
                }
                if (!db) {
                    if (pcb == cb) db = true;
                    else { cb = pcb; taub = (psb - 1.0f) / pcb; }
                }
                if (da && db) break;
            }

            float* o0 = out + (row0 + iA) * DOUT;
            float* o1 = out + (row0 + iB) * DOUT;
            float4 v;
            v.x = fmaxf(za[0] - taua, 0.f); v.y = fmaxf(za[1] - taua, 0.f);
            v.z = fmaxf(za[2] - taua, 0.f); v.w = fmaxf(za[3] - taua, 0.f);
            *reinterpret_cast<float4*>(&o0[lane4]) = v;
            v.x = fmaxf(za[4] - taua, 0.f); v.y = fmaxf(za[5] - taua, 0.f);
            v.z = fmaxf(za[6] - taua, 0.f); v.w = fmaxf(za[7] - taua, 0.f);
            *reinterpret_cast<float4*>(&o0[128 + lane4]) = v;
            v.x = fmaxf(zb[0] - taub, 0.f); v.y = fmaxf(zb[1] - taub, 0.f);
            v.z = fmaxf(zb[2] - taub, 0.f); v.w = fmaxf(zb[3] - taub, 0.f);
            *reinterpret_cast<float4*>(&o1[lane4]) = v;
            v.x = fmaxf(zb[4] - taub, 0.f); v.y = fmaxf(zb[5] - taub, 0.f);
            v.z = fmaxf(zb[6] - taub, 0.f); v.w = fmaxf(zb[7] - taub, 0.f);
            *reinterpret_cast<float4*>(&o1[128 + lane4]) = v;
        }

        // wait for this warp's prefetch before the next GEMM reads sA
        CP_WAIT0();
        __syncwarp();
    }
}

extern "C" void kernel_launch(void* const* d_in, const int* in_sizes, int n_in,
                              void* d_out, int out_size) {
    const float* inputs = (const float*)d_in[0];
    const float* priors = (const float*)d_in[1];
    const float* W      = (const float*)d_in[2];
    const float* gamma  = (const float*)d_in[3];
    const float* beta   = (const float*)d_in[4];
    const float* mmean  = (const float*)d_in[5];
    const float* mvar   = (const float*)d_in[6];
    float* out = (float*)d_out;

    int B = in_sizes[0] / DIN;          // 262144
    int nTiles = B / MT;                // 2048

    int dev = 0;
    cudaGetDevice(&dev);
    int nsm = 0;
    cudaDeviceGetAttribute(&nsm, cudaDevAttrMultiProcessorCount, dev);
    if (nsm <= 0) nsm = 148;
    if (nsm > nTiles) nsm = nTiles;

    cudaFuncSetAttribute(attn_transformer_kernel,
                         cudaFuncAttributeMaxDynamicSharedMemorySize, SMEM_BYTES);

    attn_transformer_kernel<<<nsm, NTHREADS, SMEM_BYTES>>>(
        inputs, priors, W, gamma, beta, mmean, mvar, out, nTiles);
}

// round 10
// speedup vs baseline: 1.3169x; 1.3169x over previous
#include <cuda_runtime.h>
#include <cstdint>

#define BN_EPS   1e-3f
#define DIN      128
#define DOUT     256
#define MT       64
#define NTHREADS 512

// smem (floats): sW[32768] | sA[16 warps][512] | sScale[256] | sBias[256]
#define SMEM_FLOATS (32768 + 8192 + 256 + 256)
#define SMEM_BYTES  (SMEM_FLOATS * 4)

__device__ __forceinline__ void ffma2(unsigned long long &d, unsigned long long a, unsigned long long b) {
    asm("fma.rn.f32x2 %0, %1, %2, %0;" : "+l"(d) : "l"(a), "l"(b));
}
__device__ __forceinline__ unsigned long long dup2(float x) {
    unsigned long long r;
    asm("mov.b64 %0, {%1, %1};" : "=l"(r) : "f"(x));
    return r;
}
__device__ __forceinline__ void unpack2(unsigned long long v, float &lo, float &hi) {
    asm("mov.b64 {%0, %1}, %2;" : "=f"(lo), "=f"(hi) : "l"(v));
}
__device__ __forceinline__ void cp_async16(float* dst_smem, const float* src) {
    unsigned s = (unsigned)__cvta_generic_to_shared(dst_smem);
    asm volatile("cp.async.cg.shared.global [%0], [%1], 16;" :: "r"(s), "l"(src));
}
#define CP_COMMIT() asm volatile("cp.async.commit_group;")
#define CP_WAIT0()  asm volatile("cp.async.wait_group 0;")

__global__ __launch_bounds__(NTHREADS, 1)
void attn_transformer_kernel(const float* __restrict__ inputs,
                             const float* __restrict__ priors,
                             const float* __restrict__ W,
                             const float* __restrict__ gamma,
                             const float* __restrict__ beta,
                             const float* __restrict__ mmean,
                             const float* __restrict__ mvar,
                             float* __restrict__ out,
                             int nTiles)
{
    extern __shared__ float smem[];
    float* sW     = smem;                    // [128][256]
    float* sAbase = smem + 32768;            // [16 warps][4][128]
    float* sScale = smem + 32768 + 8192;     // [256]
    float* sBias  = sScale + 256;            // [256]

    const int tid   = threadIdx.x;
    const int lane  = tid & 31;
    const int warp  = tid >> 5;
    const int lane4 = lane * 4;

    float* sA = sAbase + warp * 512;         // this warp's private 4-row buffer

    // ---- prologue ----
    // W -> smem (all threads cooperate)
    #pragma unroll
    for (int j = 0; j < 16; ++j) {
        int idx = tid + NTHREADS * j;                // float4 idx [0,8192)
        cp_async16(sW + idx * 4, W + idx * 4);
    }
    // this warp's first A rows (4 rows x 128 floats = 128 x 16B chunks)
    {
        const float* Abase = inputs + ((size_t)blockIdx.x * MT + warp * 4) * DIN;
        #pragma unroll
        for (int j = 0; j < 4; ++j) {
            int c = lane + 32 * j;                   // 16B chunk [0,128)
            cp_async16(sA + c * 4, Abase + c * 4);
        }
    }
    CP_COMMIT();

    // fold BN into scale/bias
    if (tid < 256) {
        float inv = gamma[tid] * rsqrtf(mvar[tid] + BN_EPS);
        sScale[tid] = inv;
        sBias[tid]  = beta[tid] - mmean[tid] * inv;
    }

    CP_WAIT0();
    __syncthreads();     // W + consts visible to all warps; the ONLY CTA barrier

    for (int t = blockIdx.x; t < nTiles; t += gridDim.x) {
        // ---- GEMM: 4 rows x 8 cols per thread, packed f32x2 FFMA ----
        unsigned long long acc[4][4];
        #pragma unroll
        for (int i = 0; i < 4; ++i) {
            acc[i][0] = 0ull; acc[i][1] = 0ull; acc[i][2] = 0ull; acc[i][3] = 0ull;
        }

        #pragma unroll 4
        for (int kk = 0; kk < DIN; kk += 4) {
            float4 a4[4];
            #pragma unroll
            for (int i = 0; i < 4; ++i)
                a4[i] = *reinterpret_cast<const float4*>(&sA[i * DIN + kk]);
            #pragma unroll
            for (int q = 0; q < 4; ++q) {
                const float* wrow = &sW[(kk + q) * DOUT];
                ulonglong2 Blo = *reinterpret_cast<const ulonglong2*>(&wrow[lane4]);
                ulonglong2 Bhi = *reinterpret_cast<const ulonglong2*>(&wrow[128 + lane4]);
                #pragma unroll
                for (int i = 0; i < 4; ++i) {
                    float av = (q == 0) ? a4[i].x : (q == 1) ? a4[i].y
                             : (q == 2) ? a4[i].z : a4[i].w;
                    unsigned long long ad = dup2(av);
                    ffma2(acc[i][0], ad, Blo.x);
                    ffma2(acc[i][1], ad, Blo.y);
                    ffma2(acc[i][2], ad, Bhi.x);
                    ffma2(acc[i][3], ad, Bhi.y);
                }
            }
        }

        // ---- prefetch next tile's rows into the SAME buffer (GEMM reads done);
        //      epilogue covers the flight; per-warp, no barrier ----
        {
            int tn = t + gridDim.x;
            if (tn < nTiles) {
                const float* Abase = inputs + ((size_t)tn * MT + warp * 4) * DIN;
                #pragma unroll
                for (int j = 0; j < 4; ++j) {
                    int c = lane + 32 * j;
                    cp_async16(sA + c * 4, Abase + c * 4);
                }
            }
            CP_COMMIT();
        }

        // ---- epilogue: 2 row-pairs ----
        const size_t row0 = (size_t)t * MT + warp * 4;

        #pragma unroll 1
        for (int pr = 0; pr < 2; ++pr) {
            const int iA = 2 * pr, iB = 2 * pr + 1;

            float4 scLo = *reinterpret_cast<const float4*>(&sScale[lane4]);
            float4 scHi = *reinterpret_cast<const float4*>(&sScale[128 + lane4]);
            float4 bLo  = *reinterpret_cast<const float4*>(&sBias[lane4]);
            float4 bHi  = *reinterpret_cast<const float4*>(&sBias[128 + lane4]);

            const float* prA = priors + (row0 + iA) * DOUT;
            const float* prB = priors + (row0 + iB) * DOUT;
            float4 pA0 = *reinterpret_cast<const float4*>(&prA[lane4]);
            float4 pA1 = *reinterpret_cast<const float4*>(&prA[128 + lane4]);
            float4 pB0 = *reinterpret_cast<const float4*>(&prB[lane4]);
            float4 pB1 = *reinterpret_cast<const float4*>(&prB[128 + lane4]);

            float za[8], zb[8];
            {
                float x0, x1, x2, x3, x4, x5, x6, x7;
                unpack2(acc[iA][0], x0, x1);
                unpack2(acc[iA][1], x2, x3);
                unpack2(acc[iA][2], x4, x5);
                unpack2(acc[iA][3], x6, x7);
                za[0] = fmaf(x0, scLo.x, bLo.x) * pA0.x;
                za[1] = fmaf(x1, scLo.y, bLo.y) * pA0.y;
                za[2] = fmaf(x2, scLo.z, bLo.z) * pA0.z;
                za[3] = fmaf(x3, scLo.w, bLo.w) * pA0.w;
                za[4] = fmaf(x4, scHi.x, bHi.x) * pA1.x;
                za[5] = fmaf(x5, scHi.y, bHi.y) * pA1.y;
                za[6] = fmaf(x6, scHi.z, bHi.z) * pA1.z;
                za[7] = fmaf(x7, scHi.w, bHi.w) * pA1.w;
                unpack2(acc[iB][0], x0, x1);
                unpack2(acc[iB][1], x2, x3);
                unpack2(acc[iB][2], x4, x5);
                unpack2(acc[iB][3], x6, x7);
                zb[0] = fmaf(x0, scLo.x, bLo.x) * pB0.x;
                zb[1] = fmaf(x1, scLo.y, bLo.y) * pB0.y;
                zb[2] = fmaf(x2, scLo.z, bLo.z) * pB0.z;
                zb[3] = fmaf(x3, scLo.w, bLo.w) * pB0.w;
                zb[4] = fmaf(x4, scHi.x, bHi.x) * pB1.x;
                zb[5] = fmaf(x5, scHi.y, bHi.y) * pB1.y;
                zb[6] = fmaf(x6, scHi.z, bHi.z) * pB1.z;
                zb[7] = fmaf(x7, scHi.w, bHi.w) * pB1.w;
            }

            // Michelot fixed point (two rows pipelined through the shfl chains)
            float sa = 0.f, sb = 0.f;
            #pragma unroll
            for (int j = 0; j < 8; ++j) { sa += za[j]; sb += zb[j]; }
            #pragma unroll
            for (int off = 16; off > 0; off >>= 1) {
                sa += __shfl_xor_sync(0xffffffffu, sa, off);
                sb += __shfl_xor_sync(0xffffffffu, sb, off);
            }
            float taua = (sa - 1.0f) * (1.0f / 256.0f);
            float taub = (sb - 1.0f) * (1.0f / 256.0f);
            float ca = 256.0f, cb = 256.0f;
            bool da = false, db = false;

            for (int it = 0; it < 64; ++it) {
                float psa = 0.f, pca = 0.f, psb = 0.f, pcb = 0.f;
                #pragma unroll
                for (int j = 0; j < 8; ++j) {
                    if (za[j] > taua) { psa += za[j]; pca += 1.0f; }
                    if (zb[j] > taub) { psb += zb[j]; pcb += 1.0f; }
                }
                #pragma unroll
                for (int off = 16; off > 0; off >>= 1) {
                    psa += __shfl_xor_sync(0xffffffffu, psa, off);
                    pca += __shfl_xor_sync(0xffffffffu, pca, off);
                    psb += __shfl_xor_sync(0xffffffffu, psb, off);
                    pcb += __shfl_xor_sync(0xffffffffu, pcb, off);
                }
                if (!da) {
                    if (pca == ca) da = true;
                    else { ca = pca; taua = (psa - 1.0f) / pca; }
                }
                if (!db) {
                    if (pcb == cb) db = true;
                    else { cb = pcb; taub = (psb - 1.0f) / pcb; }
                }
                if (da && db) break;
            }

            float* o0 = out + (row0 + iA) * DOUT;
            float* o1 = out + (row0 + iB) * DOUT;
            float4 v;
            v.x = fmaxf(za[0] - taua, 0.f); v.y = fmaxf(za[1] - taua, 0.f);
            v.z = fmaxf(za[2] - taua, 0.f); v.w = fmaxf(za[3] - taua, 0.f);
            *reinterpret_cast<float4*>(&o0[lane4]) = v;
            v.x = fmaxf(za[4] - taua, 0.f); v.y = fmaxf(za[5] - taua, 0.f);
            v.z = fmaxf(za[6] - taua, 0.f); v.w = fmaxf(za[7] - taua, 0.f);
            *reinterpret_cast<float4*>(&o0[128 + lane4]) = v;
            v.x = fmaxf(zb[0] - taub, 0.f); v.y = fmaxf(zb[1] - taub, 0.f);
            v.z = fmaxf(zb[2] - taub, 0.f); v.w = fmaxf(zb[3] - taub, 0.f);
            *reinterpret_cast<float4*>(&o1[lane4]) = v;
            v.x = fmaxf(zb[4] - taub, 0.f); v.y = fmaxf(zb[5] - taub, 0.f);
            v.z = fmaxf(zb[6] - taub, 0.f); v.w = fmaxf(zb[7] - taub, 0.f);
            *reinterpret_cast<float4*>(&o1[128 + lane4]) = v;
        }

        // wait for this warp's prefetch before the next GEMM reads sA
        CP_WAIT0();
        __syncwarp();
    }
}

extern "C" void kernel_launch(void* const* d_in, const int* in_sizes, int n_in,
                              void* d_out, int out_size) {
    const float* inputs = (const float*)d_in[0];
    const float* priors = (const float*)d_in[1];
    const float* W      = (const float*)d_in[2];
    const float* gamma  = (const float*)d_in[3];
    const float* beta   = (const float*)d_in[4];
    const float* mmean  = (const float*)d_in[5];
    const float* mvar   = (const float*)d_in[6];
    float* out = (float*)d_out;

    int B = in_sizes[0] / DIN;          // 262144
    int nTiles = B / MT;                // 4096

    int dev = 0;
    cudaGetDevice(&dev);
    int nsm = 0;
    cudaDeviceGetAttribute(&nsm, cudaDevAttrMultiProcessorCount, dev);
    if (nsm <= 0) nsm = 148;
    if (nsm > nTiles) nsm = nTiles;

    cudaFuncSetAttribute(attn_transformer_kernel,
                         cudaFuncAttributeMaxDynamicSharedMemorySize, SMEM_BYTES);

    attn_transformer_kernel<<<nsm, NTHREADS, SMEM_BYTES>>>(
        inputs, priors, W, gamma, beta, mmean, mvar, out, nTiles);
}